// round 10
// baseline (speedup 1.0000x reference)
#include <cuda_runtime.h>
#include <cuda_bf16.h>
#include <cstdint>

// Gather: out[i, y, x, c] = logits[i * N_SP + segments[i, y, x], c]
//   logits:   [16*512, 5] fp32 (10 KB per image, TMA bulk-loaded into smem)
//   segments: [16, 512, 512] int32 (8 KB tile per block, TMA bulk-loaded)
//   out:      [16, 512, 512, 5] fp32
//
// R10 = R9 (best: TMA staging + 320thr x 8 iters) with the hot loop split
// into an explicit two-phase pipeline: all 16 seg LDS issued first (MLP 16),
// then the 32 gather LDS + 8 STG. R9's regs=32 forced ptxas to serialize the
// 8 unrolled iterations (false register deps exposing ~60cyc LDS latency per
// iter). __launch_bounds__(320,5) -> 40 regs, 5 blocks/SM (50 warps).

#define N_IMG 16
#define SIZE  512
#define N_SP  512
#define WAY   5
#define PIX_PER_IMG    (SIZE * SIZE)            // 262144
#define VEC_PER_IMG    (PIX_PER_IMG * WAY / 4)  // 327680 float4
#define LOGITS_PER_IMG (N_SP * WAY)             // 2560 floats = 10240 B

#define THREADS 320
#define ITERS 8
#define VEC_PER_BLOCK  (THREADS * ITERS)        // 2560 float4
#define PIX_PER_BLOCK  (VEC_PER_BLOCK * 4 / WAY)// 2048 pixels (exact)
#define PIX_PER_ITER   (THREADS * 4 / WAY)      // 256 pixels
#define BLOCKS_PER_IMG (VEC_PER_IMG / VEC_PER_BLOCK) // 128

#define LOGITS_BYTES (LOGITS_PER_IMG * 4)       // 10240
#define SEG_BYTES    (PIX_PER_BLOCK * 4)        // 8192
#define TOTAL_TX     (LOGITS_BYTES + SEG_BYTES) // 18432

__device__ __forceinline__ uint32_t smem_u32(const void* p) {
    uint32_t a;
    asm("{ .reg .u64 t; cvta.to.shared.u64 t, %1; cvt.u32.u64 %0, t; }"
        : "=r"(a) : "l"(p));
    return a;
}

__global__ void __launch_bounds__(THREADS, 5)
sp_gather_kernel10(const float* __restrict__ logits,
                   const int* __restrict__ seg,
                   float4* __restrict__ out)
{
    __shared__ __align__(16) float    s_logits[LOGITS_PER_IMG];
    __shared__ __align__(16) int      s_seg[PIX_PER_BLOCK];
    __shared__ __align__(8)  uint64_t s_mbar;

    const int img = blockIdx.y;
    const int blk = blockIdx.x;
    const int tid = threadIdx.x;

    // ---- Staging via two cp.async.bulk G->S copies, one mbarrier ----
    if (tid == 0) {
        uint32_t mb = smem_u32(&s_mbar);
        asm volatile("mbarrier.init.shared.b64 [%0], 1;" :: "r"(mb) : "memory");
    }
    __syncthreads();

    if (tid == 0) {
        uint32_t mb = smem_u32(&s_mbar);
        asm volatile("mbarrier.arrive.expect_tx.shared.b64 _, [%0], %1;"
                     :: "r"(mb), "n"(TOTAL_TX) : "memory");
        uint32_t dl = smem_u32(s_logits);
        const void* sl = logits + (size_t)img * LOGITS_PER_IMG;
        asm volatile(
            "cp.async.bulk.shared::cta.global.mbarrier::complete_tx::bytes "
            "[%0], [%1], %2, [%3];"
            :: "r"(dl), "l"(sl), "n"(LOGITS_BYTES), "r"(mb) : "memory");
        uint32_t ds = smem_u32(s_seg);
        const void* ss = seg + (size_t)img * PIX_PER_IMG
                             + (size_t)blk * PIX_PER_BLOCK;
        asm volatile(
            "cp.async.bulk.shared::cta.global.mbarrier::complete_tx::bytes "
            "[%0], [%1], %2, [%3];"
            :: "r"(ds), "l"(ss), "n"(SEG_BYTES), "r"(mb) : "memory");
    }

    // Wait (acquire orders subsequent LDS after the TMA writes).
    {
        uint32_t mb = smem_u32(&s_mbar);
        uint32_t done;
        asm volatile(
            "{\n\t"
            ".reg .pred p;\n\t"
            "mbarrier.try_wait.parity.acquire.cta.shared::cta.b64 p, [%1], 0;\n\t"
            "selp.b32 %0, 1, 0, p;\n\t"
            "}" : "=r"(done) : "r"(mb) : "memory");
        if (!done) {
            asm volatile(
                "{\n\t"
                ".reg .pred P1;\n\t"
                "WL_%=:\n\t"
                "mbarrier.try_wait.parity.acquire.cta.shared::cta.b64 P1, [%0], 0, 0x989680;\n\t"
                "@P1 bra.uni WD_%=;\n\t"
                "bra.uni WL_%=;\n\t"
                "WD_%=:\n\t"
                "}" :: "r"(mb) : "memory");
        }
    }

    // ---- Hot loop: two-phase pipeline ----
    float4* out_img = out + (size_t)img * VEC_PER_IMG;
    const int jbase = blk * VEC_PER_BLOCK + tid;

    const int floc = tid << 2;            // 0..1276
    const int p0   = floc / 5;            // 0..255
    const int r    = floc - 5 * p0;       // constant channel remainder 0..4
    const int m    = 5 - r;
    const bool need_s1 = (r >= 2);        // s1 used only when m < 4

    // Phase A: all seg loads in flight, compute gather bases.
    int b0[ITERS], b1[ITERS];
#pragma unroll
    for (int it = 0; it < ITERS; ++it) {
        const int p = p0 + it * PIX_PER_ITER;   // compile-time offsets
        b0[it] = s_seg[p] * WAY + r;
        b1[it] = need_s1 ? (s_seg[p + 1] * WAY + r - 5) : 0;
    }

    // Phase B: gathers + coalesced stores.
#pragma unroll
    for (int it = 0; it < ITERS; ++it) {
        float v0 = s_logits[((0 < m) ? b0[it] : b1[it]) + 0];
        float v1 = s_logits[((1 < m) ? b0[it] : b1[it]) + 1];
        float v2 = s_logits[((2 < m) ? b0[it] : b1[it]) + 2];
        float v3 = s_logits[((3 < m) ? b0[it] : b1[it]) + 3];
        out_img[jbase + it * THREADS] = make_float4(v0, v1, v2, v3);
    }
}

extern "C" void kernel_launch(void* const* d_in, const int* in_sizes, int n_in,
                              void* d_out, int out_size)
{
    const float* logits = (const float*)d_in[0];
    const int*   seg    = (const int*)d_in[1];
    float4*      out    = (float4*)d_out;

    dim3 grid(BLOCKS_PER_IMG, N_IMG);
    sp_gather_kernel10<<<grid, THREADS>>>(logits, seg, out);
}